// round 11
// baseline (speedup 1.0000x reference)
#include <cuda_runtime.h>
#include <cstdint>
#include <cstddef>

// out[n, l, o] = weight[o, l]   for n in [0,128), l,o in [0,1024)
// Two-kernel pipeline:
//   A: transpose weight -> out[0]            (4 MB, required output anyway)
//   B: broadcast out[0] -> planes 1..127     (508 MB, L2-resident source,
//      single coalesced LDG.128 prologue, no smem, no barrier, __stcs stores)
// B keeps R8's proven granularity: 32768 blocks, 16 KB stores per block.

namespace {
constexpr int L   = 1024;
constexpr int OUT = 1024;
constexpr int N   = 128;

// Kernel A tiling (transpose 1024x1024 into plane 0)
constexpr int TL = 32;
constexpr int TO = 32;
constexpr int THREADS_A = 256;

// Kernel B tiling
constexpr int THREADS_B = 256;
constexpr int CHUNK = THREADS_B * 4;           // 1024 floats per block (4 KB)
constexpr int XB = (L * OUT) / CHUNK;          // 1024 x-blocks
constexpr int ZB = 32;                          // planes 1..127 over 32 z-slices
}

__global__ __launch_bounds__(THREADS_A)
void lfd_transpose_plane0(const float* __restrict__ w,
                          float* __restrict__ out) {
    __shared__ __align__(16) float tile[TL][TO + 4];

    const int l0 = blockIdx.x * TL;
    const int o0 = blockIdx.y * TO;
    const int tid = threadIdx.x;

    // Load weight tile [o0:o0+32, l0:l0+32], transposing into smem.
    {
        const int r = tid >> 3;       // o offset: 0..31
        const int c = tid & 7;        // l float4 column: 0..7
        const float4 v = *reinterpret_cast<const float4*>(
            &w[(size_t)(o0 + r) * L + l0 + c * 4]);
        tile[c * 4 + 0][r] = v.x;
        tile[c * 4 + 1][r] = v.y;
        tile[c * 4 + 2][r] = v.z;
        tile[c * 4 + 3][r] = v.w;
    }
    __syncthreads();

    const int l_a = tid >> 3;
    const int c_a = tid & 7;
    const float4 va = *reinterpret_cast<const float4*>(&tile[l_a][c_a * 4]);
    // Plane 0 store: normal policy (we WANT these lines to stay in L2 for B).
    *reinterpret_cast<float4*>(&out[(size_t)(l0 + l_a) * OUT + o0 + c_a * 4]) = va;
}

__global__ __launch_bounds__(THREADS_B)
void lfd_broadcast(const float* __restrict__ src,   // = out plane 0
                   float* __restrict__ out) {
    const size_t off = (size_t)blockIdx.x * CHUNK + threadIdx.x * 4;
    const float4 v = *reinterpret_cast<const float4*>(src + off);

    const size_t plane = (size_t)L * OUT;
    const int z = blockIdx.y;
    const int n_start = 1 + 4 * z;                // z=0 ->1, ..., z=31 ->125
    const int cnt = (z == ZB - 1) ? 3 : 4;        // planes 1..127

    size_t base = (size_t)n_start * plane + off;
#pragma unroll 4
    for (int i = 0; i < cnt; i++) {
        __stcs(reinterpret_cast<float4*>(&out[base]), v);
        base += plane;
    }
}

extern "C" void kernel_launch(void* const* d_in, const int* in_sizes, int n_in,
                              void* d_out, int out_size) {
    // d_in[0] = x (unused — reference discards net(x)), d_in[1] = weight [1024,1024]
    const float* weight = (const float*)d_in[1];
    float* out = (float*)d_out;

    dim3 gridA(L / TL, OUT / TO);                  // (32, 32) = 1024 blocks
    lfd_transpose_plane0<<<gridA, THREADS_A>>>(weight, out);

    dim3 gridB(XB, ZB);                            // (1024, 32) = 32768 blocks
    lfd_broadcast<<<gridB, THREADS_B>>>(out, out);
}

// round 12
// speedup vs baseline: 1.2509x; 1.2509x over previous
#include <cuda_runtime.h>
#include <cstdint>
#include <cstddef>

// out[n, l, o] = weight[o, l]   for n in [0,128), l,o in [0,1024)
// 512 MB broadcast-write of weight.T; smem transpose -> register -> __stcs
// replicate-stores (proven structure; two-kernel copy variant regressed).
// DRAM duty vs blocks: 4096:79.1%, 8192:79.5%, 16384:81.5%, 32768:82.4%.
// Round 12: 65536 blocks while HOLDING 4 STG/thread (TL 32->16, 128 thr)
// to disentangle the R9 cliff (which halved STG/thread AND doubled blocks).

namespace {
constexpr int L   = 1024;
constexpr int OUT = 1024;
constexpr int N   = 128;

constexpr int TL = 16;   // tile extent along l (halved vs R8)
constexpr int TO = 32;   // tile extent along o
constexpr int NZ = 32;   // grid (64,32,32) = 65536 blocks
constexpr int N_PER_BLOCK = N / NZ;  // 4 planes per block -> 4 STG/thread
constexpr int THREADS = 128;
}

__global__ __launch_bounds__(THREADS)
void linfwddiff_bcast_fine64k(const float* __restrict__ w,
                              float* __restrict__ out) {
    // Padded transpose tile: tile[l][o]; row stride 36 floats (no bank conflicts).
    __shared__ __align__(16) float tile[TL][TO + 4];

    const int l0 = blockIdx.x * TL;
    const int o0 = blockIdx.y * TO;
    const int n0 = blockIdx.z * N_PER_BLOCK;
    const int tid = threadIdx.x;

    // ---- Load weight tile [o0:o0+32, l0:l0+16], transposing into smem ----
    // 32 rows (o) x 4 float4 (l) = 128 slots; 1 per thread.
    {
        const int r = tid >> 2;       // o offset within tile: 0..31
        const int c = tid & 3;        // l float4 column:      0..3
        const float4 v = *reinterpret_cast<const float4*>(
            &w[(size_t)(o0 + r) * L + l0 + c * 4]);
        tile[c * 4 + 0][r] = v.x;
        tile[c * 4 + 1][r] = v.y;
        tile[c * 4 + 2][r] = v.z;
        tile[c * 4 + 3][r] = v.w;
    }
    __syncthreads();

    // ---- Hoist transposed values into registers (1 float4 per thread) ----
    // 16 rows (l) x 8 float4 (o) = 128 slots; 1 per thread.
    const int l_a = tid >> 3;         // l within tile: 0..15
    const int c_a = tid & 7;          // o float4 column: 0..7
    const float4 va = *reinterpret_cast<const float4*>(&tile[l_a][c_a * 4]);

    const size_t plane = (size_t)L * OUT;                       // 1M elements
    const size_t offa = (size_t)(l0 + l_a) * OUT + o0 + c_a * 4;
    size_t base = (size_t)n0 * plane;

    // ---- Replicate-store across n: pure STG.128 stream, evict-first ----
#pragma unroll
    for (int n = 0; n < N_PER_BLOCK; n++) {
        __stcs(reinterpret_cast<float4*>(&out[base + offa]), va);
        base += plane;
    }
}

extern "C" void kernel_launch(void* const* d_in, const int* in_sizes, int n_in,
                              void* d_out, int out_size) {
    // d_in[0] = x (unused — reference discards net(x)), d_in[1] = weight [1024,1024]
    const float* weight = (const float*)d_in[1];
    float* out = (float*)d_out;

    dim3 grid(L / TL, OUT / TO, NZ);   // (64, 32, 32) = 65536 blocks
    linfwddiff_bcast_fine64k<<<grid, THREADS>>>(weight, out);
}